// round 7
// baseline (speedup 1.0000x reference)
#include <cuda_runtime.h>
#include <cuda_bf16.h>
#include <math.h>

#define Bsz 16
#define Lsz 4096
#define Hsz 128
#define N2 32
#define NL 4
#define O2 256
#define DOUT 100
#define Q 128
#define NC (Lsz / Q)   // 32

typedef unsigned long long u64;
typedef unsigned int u32;

// ---------------- f32x2 packed helpers ----------------
__device__ __forceinline__ u64 pk(float a, float b) {
    u64 r; asm("mov.b64 %0,{%1,%2};" : "=l"(r) : "f"(a), "f"(b)); return r;
}
__device__ __forceinline__ float2 upk(u64 v) {
    float2 r; asm("mov.b64 {%0,%1},%2;" : "=f"(r.x), "=f"(r.y) : "l"(v)); return r;
}
__device__ __forceinline__ u64 fma2(u64 a, u64 b, u64 c) {
    u64 r; asm("fma.rn.f32x2 %0,%1,%2,%3;" : "=l"(r) : "l"(a), "l"(b), "l"(c)); return r;
}
__device__ __forceinline__ u64 mul2(u64 a, u64 b) {
    u64 r; asm("mul.rn.f32x2 %0,%1,%2;" : "=l"(r) : "l"(a), "l"(b)); return r;
}
__device__ __forceinline__ u64 add2(u64 a, u64 b) {
    u64 r; asm("add.rn.f32x2 %0,%1,%2;" : "=l"(r) : "l"(a), "l"(b)); return r;
}
__device__ __forceinline__ u32 to_tf32(float x) {
    u32 r; asm("cvt.rna.tf32.f32 %0, %1;" : "=r"(r) : "f"(x)); return r;
}
__device__ __forceinline__ void mma_tf32(float c[4], const u32 a[4], const u32 b[2]) {
    asm volatile("mma.sync.aligned.m16n8k8.row.col.f32.tf32.tf32.f32 "
                 "{%0,%1,%2,%3}, {%4,%5,%6,%7}, {%8,%9}, {%0,%1,%2,%3};"
                 : "+f"(c[0]), "+f"(c[1]), "+f"(c[2]), "+f"(c[3])
                 : "r"(a[0]), "r"(a[1]), "r"(a[2]), "r"(a[3]), "r"(b[0]), "r"(b[1]));
}

// ---------------- scratch (device globals; no allocation) ----------------
__device__ float  d_hact[Bsz * Hsz * Lsz];   // activation, layout (B,H,L)
__device__ float  d_gbuf[Bsz * Hsz * Lsz];   // gelu output (GEMM input)
__device__ float4 d_rc[NL * Hsz * N2];       // {r.re, r.im, 2Cd.re, 2Cd.im}
__device__ float2 d_rq[NL * Hsz * N2];       // r^Q
__device__ ulonglong2 d_vt[NL * Hsz * Q * 16]; // v[j] = r^{Q-1-j}, packed pairs {re2, im2}
__device__ float  d_pool[Bsz * Hsz];

// ---------------- prep: discretize SSM params ----------------
__global__ void prep_kernel(const float* __restrict__ log_dt,
                            const float* __restrict__ Cp,
                            const float* __restrict__ logAre,
                            const float* __restrict__ Aimp) {
    int idx = blockIdx.x * 256 + threadIdx.x;
    if (idx >= NL * Hsz * N2) return;
    int h = (idx >> 5) & 127;
    int layer = idx >> 12;
    float dt  = expf(log_dt[layer * Hsz + h]);
    float Are = -expf(logAre[idx]);
    float Ai  = Aimp[idx];
    float dre = Are * dt, dim = Ai * dt;
    float er  = expf(dre);
    float rre = er * cosf(dim), rim = er * sinf(dim);
    float den = Are * Are + Ai * Ai;
    float nre = rre - 1.0f, nim = rim;
    float fre = (nre * Are + nim * Ai) / den;
    float fim = (nim * Are - nre * Ai) / den;
    float Cre = Cp[idx * 2], Cim = Cp[idx * 2 + 1];
    float cdre = 2.0f * (Cre * fre - Cim * fim);
    float cdim = 2.0f * (Cre * fim + Cim * fre);
    d_rc[idx] = make_float4(rre, rim, cdre, cdim);
    float qr = rre, qi = rim;
#pragma unroll
    for (int i = 0; i < 7; i++) {
        float a = qr * qr - qi * qi;
        float b = 2.0f * qr * qi;
        qr = a; qi = b;
    }
    d_rq[idx] = make_float2(qr, qi);
}

// ---------------- prep_v: Vandermonde table v[j] = r^{Q-1-j} ----------------
__global__ void prepv_kernel(const float* __restrict__ log_dt,
                             const float* __restrict__ logAre,
                             const float* __restrict__ Aimp) {
    int idx = blockIdx.x * 256 + threadIdx.x;   // over NL*H*Q*16
    if (idx >= NL * Hsz * Q * 16) return;
    int p = idx & 15;
    int j = (idx >> 4) & 127;
    int h = (idx >> 11) & 127;
    int layer = idx >> 18;
    float dt = expf(log_dt[layer * Hsz + h]);
    float e = (float)(Q - 1 - j);
    float vr[2], vi[2];
#pragma unroll
    for (int m = 0; m < 2; m++) {
        int pi = ((layer * Hsz + h) << 5) + 2 * p + m;
        float Are = -expf(logAre[pi]);
        float Ai  = Aimp[pi];
        float mag = expf(Are * dt * e);
        float s, c;
        sincosf(Ai * dt * e, &s, &c);
        vr[m] = mag * c;
        vi[m] = mag * s;
    }
    ulonglong2 o;
    o.x = pk(vr[0], vr[1]);
    o.y = pk(vi[0], vi[1]);
    d_vt[idx] = o;
}

// ---------------- encoder: (B,L,1) -> (B,H,L) ----------------
__global__ void enc_kernel(const float* __restrict__ x,
                           const float* __restrict__ ew,
                           const float* __restrict__ eb) {
    int idx = blockIdx.x * 256 + threadIdx.x;
    if (idx >= Bsz * Hsz * (Lsz / 4)) return;
    int l4 = idx & ((Lsz / 4) - 1);
    int h  = (idx >> 10) & 127;
    int b  = idx >> 17;
    float4 xv = ((const float4*)x)[b * (Lsz / 4) + l4];
    float w = ew[h], bb = eb[h];
    float4 o = make_float4(xv.x * w + bb, xv.y * w + bb, xv.z * w + bb, xv.w * w + bb);
    *(float4*)(d_hact + ((size_t)(b * Hsz + h)) * Lsz + l4 * 4) = o;
}

// ---- fused scan: table dot (end states) + carry + c-folded rescan + GELU ----
__global__ void __launch_bounds__(64) scan_kernel(int layer, const float* __restrict__ Dp) {
    __shared__ float2 swT[NC * N2];
    int bh = blockIdx.x;
    int tid = threadIdx.x;
    int chunk = tid >> 1, half = tid & 1;
    int h = bh & 127;

    u64 z = pk(0.0f, 0.0f);
    u64 wre[8], wim[8];
#pragma unroll
    for (int k = 0; k < 8; k++) { wre[k] = z; wim[k] = z; }

    const float4* up4 = (const float4*)(d_hact + (size_t)bh * Lsz + chunk * Q);
    const ulonglong2* vt = d_vt + ((size_t)(layer * Hsz + h)) * Q * 16 + (half << 3);

    // ---- phase A: chunk end-state via Vandermonde dot product ----
#pragma unroll 1
    for (int j4 = 0; j4 < Q / 4; j4++) {
        float4 uv = up4[j4];
        float us[4] = {uv.x, uv.y, uv.z, uv.w};
#pragma unroll
        for (int s = 0; s < 4; s++) {
            u64 u2 = pk(us[s], us[s]);
            const ulonglong2* vj = vt + (j4 * 4 + s) * 16;
#pragma unroll
            for (int k = 0; k < 8; k++) {
                ulonglong2 v = vj[k];
                wre[k] = fma2(v.x, u2, wre[k]);
                wim[k] = fma2(v.y, u2, wim[k]);
            }
        }
    }
    {
        float2* we = &swT[chunk * N2 + (half << 4)];
#pragma unroll
        for (int k = 0; k < 8; k++) {
            float2 a = upk(wre[k]), bI = upk(wim[k]);
            we[2 * k]     = make_float2(a.x, bI.x);
            we[2 * k + 1] = make_float2(a.y, bI.y);
        }
    }
    __syncthreads();

    // ---- carry scan across chunks (warp 0, lane = mode) ----
    if (tid < 32) {
        float2 q = d_rq[((layer << 7) + h) * N2 + tid];
        float tr = 0.0f, ti = 0.0f;
#pragma unroll
        for (int c = 0; c < NC; c++) {
            float2 e = swT[c * N2 + tid];
            swT[c * N2 + tid] = make_float2(tr, ti);
            float a = tr * q.x - ti * q.y + e.x;
            ti = tr * q.y + ti * q.x + e.y;
            tr = a;
        }
    }
    __syncthreads();

    // ---- phase B: c-folded rescan with carried initial state, emit GELU ----
    const float4* rcp = &d_rc[((layer << 7) + h) * N2 + (half << 4)];
    u64 rre[8], rim[8], nri[8], cre[8], nci[8];
#pragma unroll
    for (int k = 0; k < 8; k++) {
        float4 a = rcp[2 * k], c = rcp[2 * k + 1];
        rre[k] = pk(a.x, c.x);
        rim[k] = pk(a.y, c.y);
        nri[k] = pk(-a.y, -c.y);
        cre[k] = pk(a.z, c.z);
        nci[k] = pk(-a.w, -c.w);
    }
    {
        const float2* Tp = &swT[chunk * N2 + (half << 4)];
#pragma unroll
        for (int k = 0; k < 8; k++) {
            float2 t0 = Tp[2 * k], t1 = Tp[2 * k + 1];
            wre[k] = pk(t0.x, t1.x);
            wim[k] = pk(t0.y, t1.y);
        }
    }
    float dh = Dp[(layer << 7) + h];
    float* gp = d_gbuf + (size_t)bh * Lsz + chunk * Q;
#pragma unroll 1
    for (int j4 = 0; j4 < Q / 4; j4++) {
        float4 uv = up4[j4];
        float us[4] = {uv.x, uv.y, uv.z, uv.w};
        float ys[4];
#pragma unroll
        for (int s = 0; s < 4; s++) {
            u64 u2 = pk(us[s], us[s]);
            u64 y1 = z, y2 = z;
#pragma unroll
            for (int k = 0; k < 8; k++) {
                u64 nr = fma2(rre[k], wre[k], fma2(nri[k], wim[k], u2));
                wim[k] = fma2(rre[k], wim[k], mul2(rim[k], wre[k]));
                wre[k] = nr;
                y1 = fma2(cre[k], nr, y1);
                y2 = fma2(nci[k], wim[k], y2);
            }
            float2 yy = upk(add2(y1, y2));
            float y = yy.x + yy.y;
            y += __shfl_xor_sync(0xffffffffu, y, 1);
            ys[s] = y + dh * us[s];
        }
        // GELU split across the lane pair: each lane erfs 2 of 4
        float a0 = ys[2 * half], a1 = ys[2 * half + 1];
        float g0 = 0.5f * a0 * (1.0f + erff(a0 * 0.70710678118654752f));
        float g1 = 0.5f * a1 * (1.0f + erff(a1 * 0.70710678118654752f));
        float o0 = __shfl_xor_sync(0xffffffffu, g0, 1);
        float o1 = __shfl_xor_sync(0xffffffffu, g1, 1);
        if (!half) *(float4*)(gp + j4 * 4) = make_float4(g0, g1, o0, o1);
    }
}

// ------- GLU GEMM (tf32 mma, reg-prefetch) + bias + GLU + residual + LN ----
#define WPITCH 36
#define GPITCH 72
__global__ void __launch_bounds__(256) gluln_kernel(const float* __restrict__ Wp,
                                                    const float* __restrict__ bp,
                                                    const float* __restrict__ lgp,
                                                    const float* __restrict__ lbp,
                                                    int layer) {
    __shared__ __align__(16) char smbuf[46080];   // Ws[256][36] u32 | Gs[32][72] u32 ; reused as sout[128][72] f32
    __shared__ float smu[64], srs[64];
    __shared__ float sp1[4][64], sp2[4][64];
    u32*   Ws   = (u32*)smbuf;                    // 36864 B
    u32*   Gs   = (u32*)(smbuf + 36864);          // 9216 B
    float* sout = (float*)smbuf;

    int t = threadIdx.x;
    int w = t >> 5;
    int lane = t & 31;
    int grp = lane >> 2, t4 = lane & 3;
    int b = blockIdx.y;
    int l0 = blockIdx.x << 6;
    const float* Wl = Wp + layer * O2 * Hsz;

    float acc[2][8][4];
#pragma unroll
    for (int m = 0; m < 2; m++)
#pragma unroll
        for (int n = 0; n < 8; n++)
#pragma unroll
            for (int i = 0; i < 4; i++) acc[m][n][i] = 0.0f;

    int wo = t >> 3, wk4 = t & 7;      // W staging: o-lane, k4-lane
    int gl4 = t & 15, gk = t >> 4;     // G staging

    float4 wreg[8], greg[2];
    // prologue: prefetch chunk 0
#pragma unroll
    for (int r = 0; r < 8; r++)
        wreg[r] = *(const float4*)(Wl + (r * 32 + wo) * Hsz + wk4 * 4);
#pragma unroll
    for (int r = 0; r < 2; r++)
        greg[r] = *(const float4*)(d_gbuf + ((size_t)(b * Hsz + r * 16 + gk)) * Lsz + l0 + gl4 * 4);

#pragma unroll 1
    for (int kc = 0; kc < 4; kc++) {
        // commit prefetched chunk to shared (tf32-converted)
#pragma unroll
        for (int r = 0; r < 8; r++) {
            u32* d = &Ws[(r * 32 + wo) * WPITCH + wk4 * 4];
            d[0] = to_tf32(wreg[r].x); d[1] = to_tf32(wreg[r].y);
            d[2] = to_tf32(wreg[r].z); d[3] = to_tf32(wreg[r].w);
        }
#pragma unroll
        for (int r = 0; r < 2; r++) {
            u32* d = &Gs[(r * 16 + gk) * GPITCH + gl4 * 4];
            d[0] = to_tf32(greg[r].x); d[1] = to_tf32(greg[r].y);
            d[2] = to_tf32(greg[r].z); d[3] = to_tf32(greg[r].w);
        }
        __syncthreads();

        // prefetch next chunk while MMAs run
        if (kc < 3) {
            int kn = (kc + 1) * 32;
#pragma unroll
            for (int r = 0; r < 8; r++)
                wreg[r] = *(const float4*)(Wl + (r * 32 + wo) * Hsz + kn + wk4 * 4);
#pragma unroll
            for (int r = 0; r < 2; r++)
                greg[r] = *(const float4*)(d_gbuf + ((size_t)(b * Hsz + kn + r * 16 + gk)) * Lsz + l0 + gl4 * 4);
        }

#pragma unroll
        for (int k8 = 0; k8 < 4; k8++) {
            int kb = k8 * 8;
            u32 a[2][4];
#pragma unroll
            for (int m = 0; m < 2; m++) {
                int ob = (m << 7) + (w << 4);
                a[m][0] = Ws[(ob + grp) * WPITCH + kb + t4];
                a[m][1] = Ws[(ob + grp + 8) * WPITCH + kb + t4];
                a[m][2] = Ws[(ob + grp) * WPITCH + kb + t4 + 4];
                a[m][3] = Ws[(ob + grp + 8) * WPITCH + kb + t4 + 4];
            }
            u32 bf[8][2];
#pragma unroll
            for (int n = 0; n < 8; n++) {
                bf[n][0] = Gs[(kb + t4) * GPITCH + n * 8 + grp];
                bf[n][1] = Gs[(kb + t4 + 4) * GPITCH + n * 8 + grp];
            }
#pragma unroll
            for (int m = 0; m < 2; m++)
#pragma unroll
                for (int n = 0; n < 8; n++)
                    mma_tf32(acc[m][n], a[m], bf[n]);
        }
        __syncthreads();
    }

    // epilogue: bias + GLU + residual -> sout
    const float* bl = bp + layer * O2;
    int row0 = (w << 4) + grp;         // 'a' row (0..127); gate row = row0 + 128
    float ba0 = bl[row0],       ba1 = bl[row0 + 8];
    float bg0 = bl[row0 + 128], bg1 = bl[row0 + 136];
#pragma unroll
    for (int n = 0; n < 8; n++) {
        int col = n * 8 + 2 * t4;
        size_t g0 = ((size_t)(b * Hsz) + row0) * Lsz + l0 + col;
        float2 r0 = *(const float2*)(d_hact + g0);
        float2 r1 = *(const float2*)(d_hact + g0 + (size_t)8 * Lsz);
        float za0 = acc[0][n][0] + ba0, za1 = acc[0][n][1] + ba0;
        float za2 = acc[0][n][2] + ba1, za3 = acc[0][n][3] + ba1;
        float zg0 = acc[1][n][0] + bg0, zg1 = acc[1][n][1] + bg0;
        float zg2 = acc[1][n][2] + bg1, zg3 = acc[1][n][3] + bg1;
        zg0 = 1.0f / (1.0f + expf(-zg0));
        zg1 = 1.0f / (1.0f + expf(-zg1));
        zg2 = 1.0f / (1.0f + expf(-zg2));
        zg3 = 1.0f / (1.0f + expf(-zg3));
        float o0 = za0 * zg0 + r0.x, o1 = za1 * zg1 + r0.y;
        float o2 = za2 * zg2 + r1.x, o3 = za3 * zg3 + r1.y;
        *(float2*)&sout[row0 * GPITCH + col]       = make_float2(o0, o1);
        *(float2*)&sout[(row0 + 8) * GPITCH + col] = make_float2(o2, o3);
    }
    __syncthreads();

    // LayerNorm over channel dim (128) for each of the 64 l's
    {
        int lq = t & 63, qq = t >> 6;
        float sm = 0.0f, sq = 0.0f;
#pragma unroll 8
        for (int hh = qq * 32; hh < qq * 32 + 32; hh++) {
            float v = sout[hh * GPITCH + lq];
            sm += v; sq += v * v;
        }
        sp1[qq][lq] = sm; sp2[qq][lq] = sq;
    }
    __syncthreads();
    if (t < 64) {
        float s  = sp1[0][t] + sp1[1][t] + sp1[2][t] + sp1[3][t];
        float s2 = sp2[0][t] + sp2[1][t] + sp2[2][t] + sp2[3][t];
        float m = s * (1.0f / 128.0f);
        float var = s2 * (1.0f / 128.0f) - m * m;
        smu[t] = m;
        srs[t] = rsqrtf(var + 1e-5f);
    }
    __syncthreads();

    for (int i = t; i < 2048; i += 256) {
        int hh = i >> 4, jj = (i & 15) << 2;
        float g = lgp[(layer << 7) + hh], bb = lbp[(layer << 7) + hh];
        const float* sp = &sout[hh * GPITCH + jj];
        float4 o;
        o.x = (sp[0] - smu[jj])     * srs[jj]     * g + bb;
        o.y = (sp[1] - smu[jj + 1]) * srs[jj + 1] * g + bb;
        o.z = (sp[2] - smu[jj + 2]) * srs[jj + 2] * g + bb;
        o.w = (sp[3] - smu[jj + 3]) * srs[jj + 3] * g + bb;
        *(float4*)(d_hact + ((size_t)(b * Hsz + hh)) * Lsz + l0 + jj) = o;
    }
}

// ---------------- mean pool over L ----------------
__global__ void pool_kernel() {
    int bh = blockIdx.x;
    int t = threadIdx.x;
    const float4* p = (const float4*)(d_hact + (size_t)bh * Lsz);
    float sm = 0.0f;
    for (int i = t; i < Lsz / 4; i += 128) {
        float4 v = p[i];
        sm += v.x + v.y + v.z + v.w;
    }
#pragma unroll
    for (int o = 16; o; o >>= 1) sm += __shfl_xor_sync(0xffffffffu, sm, o);
    __shared__ float sh[4];
    if ((t & 31) == 0) sh[t >> 5] = sm;
    __syncthreads();
    if (t == 0) d_pool[bh] = (sh[0] + sh[1] + sh[2] + sh[3]) * (1.0f / Lsz);
}

// ---------------- decoder ----------------
__global__ void dec_kernel(const float* __restrict__ dw,
                           const float* __restrict__ db,
                           float* __restrict__ out) {
    int b = blockIdx.x;
    int t = threadIdx.x;
    __shared__ float sp[Hsz];
    sp[t] = d_pool[b * Hsz + t];
    __syncthreads();
    if (t < DOUT) {
        float acc = db[t];
#pragma unroll 8
        for (int h = 0; h < Hsz; h++) acc += sp[h] * dw[t * Hsz + h];
        out[b * DOUT + t] = acc;
    }
}

// ---------------- launch ----------------
extern "C" void kernel_launch(void* const* d_in, const int* in_sizes, int n_in,
                              void* d_out, int out_size) {
    const float* x      = (const float*)d_in[0];
    const float* enc_w  = (const float*)d_in[1];
    const float* enc_b  = (const float*)d_in[2];
    const float* log_dt = (const float*)d_in[3];
    const float* Cp     = (const float*)d_in[4];
    const float* logAre = (const float*)d_in[5];
    const float* Aim    = (const float*)d_in[6];
    const float* Dp     = (const float*)d_in[7];
    const float* out_w  = (const float*)d_in[8];
    const float* out_b  = (const float*)d_in[9];
    const float* ln_g   = (const float*)d_in[10];
    const float* ln_b   = (const float*)d_in[11];
    const float* dec_w  = (const float*)d_in[12];
    const float* dec_b  = (const float*)d_in[13];
    float* out = (float*)d_out;

    prep_kernel<<<64, 256>>>(log_dt, Cp, logAre, Aim);
    prepv_kernel<<<(NL * Hsz * Q * 16) / 256, 256>>>(log_dt, logAre, Aim);
    enc_kernel<<<(Bsz * Hsz * (Lsz / 4) + 255) / 256, 256>>>(x, enc_w, enc_b);

    for (int layer = 0; layer < NL; layer++) {
        scan_kernel<<<Bsz * Hsz, 64>>>(layer, Dp);
        gluln_kernel<<<dim3(Lsz / 64, Bsz), 256>>>(out_w, out_b, ln_g, ln_b, layer);
    }

    pool_kernel<<<Bsz * Hsz, 128>>>();
    dec_kernel<<<Bsz, 128>>>(dec_w, dec_b, out);
}

// round 8
// speedup vs baseline: 1.2973x; 1.2973x over previous
#include <cuda_runtime.h>
#include <cuda_bf16.h>
#include <math.h>

#define Bsz 16
#define Lsz 4096
#define Hsz 128
#define N2 32
#define NL 4
#define O2 256
#define DOUT 100
#define Q 128
#define NC (Lsz / Q)   // 32

typedef unsigned long long u64;
typedef unsigned int u32;

// ---------------- f32x2 packed helpers ----------------
__device__ __forceinline__ u64 pk(float a, float b) {
    u64 r; asm("mov.b64 %0,{%1,%2};" : "=l"(r) : "f"(a), "f"(b)); return r;
}
__device__ __forceinline__ float2 upk(u64 v) {
    float2 r; asm("mov.b64 {%0,%1},%2;" : "=f"(r.x), "=f"(r.y) : "l"(v)); return r;
}
__device__ __forceinline__ u64 fma2(u64 a, u64 b, u64 c) {
    u64 r; asm("fma.rn.f32x2 %0,%1,%2,%3;" : "=l"(r) : "l"(a), "l"(b), "l"(c)); return r;
}
__device__ __forceinline__ u64 mul2(u64 a, u64 b) {
    u64 r; asm("mul.rn.f32x2 %0,%1,%2;" : "=l"(r) : "l"(a), "l"(b)); return r;
}
__device__ __forceinline__ u64 add2(u64 a, u64 b) {
    u64 r; asm("add.rn.f32x2 %0,%1,%2;" : "=l"(r) : "l"(a), "l"(b)); return r;
}
__device__ __forceinline__ u32 to_tf32(float x) {
    u32 r; asm("cvt.rna.tf32.f32 %0, %1;" : "=r"(r) : "f"(x)); return r;
}
__device__ __forceinline__ void mma_tf32(float c[4], const u32 a[4], const u32 b[2]) {
    asm volatile("mma.sync.aligned.m16n8k8.row.col.f32.tf32.tf32.f32 "
                 "{%0,%1,%2,%3}, {%4,%5,%6,%7}, {%8,%9}, {%0,%1,%2,%3};"
                 : "+f"(c[0]), "+f"(c[1]), "+f"(c[2]), "+f"(c[3])
                 : "r"(a[0]), "r"(a[1]), "r"(a[2]), "r"(a[3]), "r"(b[0]), "r"(b[1]));
}

// ---------------- scratch (device globals; no allocation) ----------------
__device__ float  d_hact[Bsz * Hsz * Lsz];   // activation, layout (B,H,L)
__device__ float  d_gbuf[Bsz * Hsz * Lsz];   // gelu output (GEMM input)
__device__ float4 d_rc[NL * Hsz * N2];       // {r.re, r.im, 2Cd.re, 2Cd.im}
__device__ float2 d_rq[NL * Hsz * N2];       // r^Q
__device__ float  d_pool[Bsz * Hsz];

// ---------------- prep: discretize SSM params ----------------
__global__ void prep_kernel(const float* __restrict__ log_dt,
                            const float* __restrict__ Cp,
                            const float* __restrict__ logAre,
                            const float* __restrict__ Aimp) {
    int idx = blockIdx.x * 256 + threadIdx.x;
    if (idx >= NL * Hsz * N2) return;
    int h = (idx >> 5) & 127;
    int layer = idx >> 12;
    float dt  = expf(log_dt[layer * Hsz + h]);
    float Are = -expf(logAre[idx]);
    float Ai  = Aimp[idx];
    float dre = Are * dt, dim = Ai * dt;
    float er  = expf(dre);
    float rre = er * cosf(dim), rim = er * sinf(dim);
    float den = Are * Are + Ai * Ai;
    float nre = rre - 1.0f, nim = rim;
    float fre = (nre * Are + nim * Ai) / den;
    float fim = (nim * Are - nre * Ai) / den;
    float Cre = Cp[idx * 2], Cim = Cp[idx * 2 + 1];
    float cdre = 2.0f * (Cre * fre - Cim * fim);
    float cdim = 2.0f * (Cre * fim + Cim * fre);
    d_rc[idx] = make_float4(rre, rim, cdre, cdim);
    float qr = rre, qi = rim;
#pragma unroll
    for (int i = 0; i < 7; i++) {
        float a = qr * qr - qi * qi;
        float b = 2.0f * qr * qi;
        qr = a; qi = b;
    }
    d_rq[idx] = make_float2(qr, qi);
}

// ---------------- encoder: (B,L,1) -> (B,H,L) ----------------
__global__ void enc_kernel(const float* __restrict__ x,
                           const float* __restrict__ ew,
                           const float* __restrict__ eb) {
    int idx = blockIdx.x * 256 + threadIdx.x;
    if (idx >= Bsz * Hsz * (Lsz / 4)) return;
    int l4 = idx & ((Lsz / 4) - 1);
    int h  = (idx >> 10) & 127;
    int b  = idx >> 17;
    float4 xv = ((const float4*)x)[b * (Lsz / 4) + l4];
    float w = ew[h], bb = eb[h];
    float4 o = make_float4(xv.x * w + bb, xv.y * w + bb, xv.z * w + bb, xv.w * w + bb);
    *(float4*)(d_hact + ((size_t)(b * Hsz + h)) * Lsz + l4 * 4) = o;
}

// ---- fused scan (c-folded state, 128 threads: 32 chunks x 4 groups) ----
// state w~ = w / c ; update w~' = r*w~ + u ; output y = sum Re(c * w~')
__global__ void __launch_bounds__(128) scan_kernel(int layer, const float* __restrict__ Dp) {
    __shared__ float2 swT[NC * N2];
    int bh = blockIdx.x;
    int tid = threadIdx.x;            // 128
    int chunk = tid >> 2, qt = tid & 3;
    int h = bh & 127;

    const float4* rcp = &d_rc[((layer << 7) + h) * N2 + (qt << 3)];  // 8 modes
    u64 rre[4], rim[4], nri[4], cre[4], nci[4];
#pragma unroll
    for (int k = 0; k < 4; k++) {
        float4 a = rcp[2 * k], c = rcp[2 * k + 1];
        rre[k] = pk(a.x, c.x);
        rim[k] = pk(a.y, c.y);
        nri[k] = pk(-a.y, -c.y);
        cre[k] = pk(a.z, c.z);
        nci[k] = pk(-a.w, -c.w);
    }
    u64 z = pk(0.0f, 0.0f);
    u64 wre[4], wim[4];
#pragma unroll
    for (int k = 0; k < 4; k++) { wre[k] = z; wim[k] = z; }

    const float4* up4 = (const float4*)(d_hact + (size_t)bh * Lsz + chunk * Q);

    // ---- phase A: chunk-local homogeneous scan (5 f32x2 per k-pair/step) ----
#pragma unroll 1
    for (int j4 = 0; j4 < Q / 4; j4++) {
        float4 uv = up4[j4];
        float us[4] = {uv.x, uv.y, uv.z, uv.w};
#pragma unroll
        for (int s = 0; s < 4; s++) {
            u64 u2 = pk(us[s], us[s]);
#pragma unroll
            for (int k = 0; k < 4; k++) {
                u64 nr = fma2(rre[k], wre[k], fma2(nri[k], wim[k], u2));
                wim[k] = fma2(rim[k], wre[k], mul2(rre[k], wim[k]));
                wre[k] = nr;
            }
        }
    }
    {
        float2* we = &swT[chunk * N2 + (qt << 3)];
#pragma unroll
        for (int k = 0; k < 4; k++) {
            float2 a = upk(wre[k]), bI = upk(wim[k]);
            we[2 * k]     = make_float2(a.x, bI.x);
            we[2 * k + 1] = make_float2(a.y, bI.y);
        }
    }
    __syncthreads();

    // ---- carry scan across chunks (warp 0, lane = mode) ----
    if (tid < 32) {
        float2 q = d_rq[((layer << 7) + h) * N2 + tid];
        float tr = 0.0f, ti = 0.0f;
#pragma unroll
        for (int c = 0; c < NC; c++) {
            float2 e = swT[c * N2 + tid];
            swT[c * N2 + tid] = make_float2(tr, ti);
            float a = tr * q.x - ti * q.y + e.x;
            ti = tr * q.y + ti * q.x + e.y;
            tr = a;
        }
    }
    __syncthreads();

    // ---- phase B: rescan with carried state, emit y + D*u, GELU ----
    {
        const float2* Tp = &swT[chunk * N2 + (qt << 3)];
#pragma unroll
        for (int k = 0; k < 4; k++) {
            float2 t0 = Tp[2 * k], t1 = Tp[2 * k + 1];
            wre[k] = pk(t0.x, t1.x);
            wim[k] = pk(t0.y, t1.y);
        }
    }
    float dh = Dp[(layer << 7) + h];
    float* gp = d_gbuf + (size_t)bh * Lsz + chunk * Q;
    int lane = tid & 31, gbase = lane & ~3;
#pragma unroll 1
    for (int j4 = 0; j4 < Q / 4; j4++) {
        float4 uv = up4[j4];
        float us[4] = {uv.x, uv.y, uv.z, uv.w};
        float ys[4];
#pragma unroll
        for (int s = 0; s < 4; s++) {
            u64 u2 = pk(us[s], us[s]);
            u64 y1 = z, y2 = z;
#pragma unroll
            for (int k = 0; k < 4; k++) {
                u64 nr = fma2(rre[k], wre[k], fma2(nri[k], wim[k], u2));
                wim[k] = fma2(rim[k], wre[k], mul2(rre[k], wim[k]));
                wre[k] = nr;
                y1 = fma2(cre[k], nr, y1);
                y2 = fma2(nci[k], wim[k], y2);
            }
            float2 yy = upk(add2(y1, y2));
            float y = yy.x + yy.y;
            y += __shfl_xor_sync(0xffffffffu, y, 1);
            y += __shfl_xor_sync(0xffffffffu, y, 2);
            ys[s] = y + dh * us[s];
        }
        // each lane erfs its quarter, reassemble by shuffle
        float a0 = ys[qt];
        float g = 0.5f * a0 * (1.0f + erff(a0 * 0.70710678118654752f));
        float o0 = __shfl_sync(0xffffffffu, g, gbase + 0);
        float o1 = __shfl_sync(0xffffffffu, g, gbase + 1);
        float o2 = __shfl_sync(0xffffffffu, g, gbase + 2);
        float o3 = __shfl_sync(0xffffffffu, g, gbase + 3);
        if (qt == 0) *(float4*)(gp + j4 * 4) = make_float4(o0, o1, o2, o3);
    }
}

// ------- GLU GEMM (tf32 mma, reg-prefetch) + bias + GLU + residual + LN ----
#define WPITCH 36
#define GPITCH 72
__global__ void __launch_bounds__(256) gluln_kernel(const float* __restrict__ Wp,
                                                    const float* __restrict__ bp,
                                                    const float* __restrict__ lgp,
                                                    const float* __restrict__ lbp,
                                                    int layer) {
    __shared__ __align__(16) char smbuf[46080];   // Ws[256][36] u32 | Gs[32][72] u32 ; reused as sout[128][72] f32
    __shared__ float smu[64], srs[64];
    __shared__ float sp1[4][64], sp2[4][64];
    u32*   Ws   = (u32*)smbuf;                    // 36864 B
    u32*   Gs   = (u32*)(smbuf + 36864);          // 9216 B
    float* sout = (float*)smbuf;

    int t = threadIdx.x;
    int w = t >> 5;
    int lane = t & 31;
    int grp = lane >> 2, t4 = lane & 3;
    int b = blockIdx.y;
    int l0 = blockIdx.x << 6;
    const float* Wl = Wp + layer * O2 * Hsz;

    float acc[2][8][4];
#pragma unroll
    for (int m = 0; m < 2; m++)
#pragma unroll
        for (int n = 0; n < 8; n++)
#pragma unroll
            for (int i = 0; i < 4; i++) acc[m][n][i] = 0.0f;

    int wo = t >> 3, wk4 = t & 7;      // W staging: o-lane, k4-lane
    int gl4 = t & 15, gk = t >> 4;     // G staging

    float4 wreg[8], greg[2];
#pragma unroll
    for (int r = 0; r < 8; r++)
        wreg[r] = *(const float4*)(Wl + (r * 32 + wo) * Hsz + wk4 * 4);
#pragma unroll
    for (int r = 0; r < 2; r++)
        greg[r] = *(const float4*)(d_gbuf + ((size_t)(b * Hsz + r * 16 + gk)) * Lsz + l0 + gl4 * 4);

#pragma unroll 1
    for (int kc = 0; kc < 4; kc++) {
#pragma unroll
        for (int r = 0; r < 8; r++) {
            u32* d = &Ws[(r * 32 + wo) * WPITCH + wk4 * 4];
            d[0] = to_tf32(wreg[r].x); d[1] = to_tf32(wreg[r].y);
            d[2] = to_tf32(wreg[r].z); d[3] = to_tf32(wreg[r].w);
        }
#pragma unroll
        for (int r = 0; r < 2; r++) {
            u32* d = &Gs[(r * 16 + gk) * GPITCH + gl4 * 4];
            d[0] = to_tf32(greg[r].x); d[1] = to_tf32(greg[r].y);
            d[2] = to_tf32(greg[r].z); d[3] = to_tf32(greg[r].w);
        }
        __syncthreads();

        if (kc < 3) {
            int kn = (kc + 1) * 32;
#pragma unroll
            for (int r = 0; r < 8; r++)
                wreg[r] = *(const float4*)(Wl + (r * 32 + wo) * Hsz + kn + wk4 * 4);
#pragma unroll
            for (int r = 0; r < 2; r++)
                greg[r] = *(const float4*)(d_gbuf + ((size_t)(b * Hsz + kn + r * 16 + gk)) * Lsz + l0 + gl4 * 4);
        }

#pragma unroll
        for (int k8 = 0; k8 < 4; k8++) {
            int kb = k8 * 8;
            u32 a[2][4];
#pragma unroll
            for (int m = 0; m < 2; m++) {
                int ob = (m << 7) + (w << 4);
                a[m][0] = Ws[(ob + grp) * WPITCH + kb + t4];
                a[m][1] = Ws[(ob + grp + 8) * WPITCH + kb + t4];
                a[m][2] = Ws[(ob + grp) * WPITCH + kb + t4 + 4];
                a[m][3] = Ws[(ob + grp + 8) * WPITCH + kb + t4 + 4];
            }
            u32 bf[8][2];
#pragma unroll
            for (int n = 0; n < 8; n++) {
                bf[n][0] = Gs[(kb + t4) * GPITCH + n * 8 + grp];
                bf[n][1] = Gs[(kb + t4 + 4) * GPITCH + n * 8 + grp];
            }
#pragma unroll
            for (int m = 0; m < 2; m++)
#pragma unroll
                for (int n = 0; n < 8; n++)
                    mma_tf32(acc[m][n], a[m], bf[n]);
        }
        __syncthreads();
    }

    // epilogue: bias + GLU + residual -> sout
    const float* bl = bp + layer * O2;
    int row0 = (w << 4) + grp;
    float ba0 = bl[row0],       ba1 = bl[row0 + 8];
    float bg0 = bl[row0 + 128], bg1 = bl[row0 + 136];
#pragma unroll
    for (int n = 0; n < 8; n++) {
        int col = n * 8 + 2 * t4;
        size_t g0 = ((size_t)(b * Hsz) + row0) * Lsz + l0 + col;
        float2 r0 = *(const float2*)(d_hact + g0);
        float2 r1 = *(const float2*)(d_hact + g0 + (size_t)8 * Lsz);
        float za0 = acc[0][n][0] + ba0, za1 = acc[0][n][1] + ba0;
        float za2 = acc[0][n][2] + ba1, za3 = acc[0][n][3] + ba1;
        float zg0 = acc[1][n][0] + bg0, zg1 = acc[1][n][1] + bg0;
        float zg2 = acc[1][n][2] + bg1, zg3 = acc[1][n][3] + bg1;
        zg0 = 1.0f / (1.0f + expf(-zg0));
        zg1 = 1.0f / (1.0f + expf(-zg1));
        zg2 = 1.0f / (1.0f + expf(-zg2));
        zg3 = 1.0f / (1.0f + expf(-zg3));
        float o0 = za0 * zg0 + r0.x, o1 = za1 * zg1 + r0.y;
        float o2 = za2 * zg2 + r1.x, o3 = za3 * zg3 + r1.y;
        *(float2*)&sout[row0 * GPITCH + col]       = make_float2(o0, o1);
        *(float2*)&sout[(row0 + 8) * GPITCH + col] = make_float2(o2, o3);
    }
    __syncthreads();

    // LayerNorm over channel dim (128) for each of the 64 l's
    {
        int lq = t & 63, qq = t >> 6;
        float sm = 0.0f, sq = 0.0f;
#pragma unroll 8
        for (int hh = qq * 32; hh < qq * 32 + 32; hh++) {
            float v = sout[hh * GPITCH + lq];
            sm += v; sq += v * v;
        }
        sp1[qq][lq] = sm; sp2[qq][lq] = sq;
    }
    __syncthreads();
    if (t < 64) {
        float s  = sp1[0][t] + sp1[1][t] + sp1[2][t] + sp1[3][t];
        float s2 = sp2[0][t] + sp2[1][t] + sp2[2][t] + sp2[3][t];
        float m = s * (1.0f / 128.0f);
        float var = s2 * (1.0f / 128.0f) - m * m;
        smu[t] = m;
        srs[t] = rsqrtf(var + 1e-5f);
    }
    __syncthreads();

    for (int i = t; i < 2048; i += 256) {
        int hh = i >> 4, jj = (i & 15) << 2;
        float g = lgp[(layer << 7) + hh], bb = lbp[(layer << 7) + hh];
        const float* sp = &sout[hh * GPITCH + jj];
        float4 o;
        o.x = (sp[0] - smu[jj])     * srs[jj]     * g + bb;
        o.y = (sp[1] - smu[jj + 1]) * srs[jj + 1] * g + bb;
        o.z = (sp[2] - smu[jj + 2]) * srs[jj + 2] * g + bb;
        o.w = (sp[3] - smu[jj + 3]) * srs[jj + 3] * g + bb;
        *(float4*)(d_hact + ((size_t)(b * Hsz + hh)) * Lsz + l0 + jj) = o;
    }
}

// ---------------- mean pool over L ----------------
__global__ void pool_kernel() {
    int bh = blockIdx.x;
    int t = threadIdx.x;
    const float4* p = (const float4*)(d_hact + (size_t)bh * Lsz);
    float sm = 0.0f;
    for (int i = t; i < Lsz / 4; i += 128) {
        float4 v = p[i];
        sm += v.x + v.y + v.z + v.w;
    }
#pragma unroll
    for (int o = 16; o; o >>= 1) sm += __shfl_xor_sync(0xffffffffu, sm, o);
    __shared__ float sh[4];
    if ((t & 31) == 0) sh[t >> 5] = sm;
    __syncthreads();
    if (t == 0) d_pool[bh] = (sh[0] + sh[1] + sh[2] + sh[3]) * (1.0f / Lsz);
}

// ---------------- decoder ----------------
__global__ void dec_kernel(const float* __restrict__ dw,
                           const float* __restrict__ db,
                           float* __restrict__ out) {
    int b = blockIdx.x;
    int t = threadIdx.x;
    __shared__ float sp[Hsz];
    sp[t] = d_pool[b * Hsz + t];
    __syncthreads();
    if (t < DOUT) {
        float acc = db[t];
#pragma unroll 8
        for (int h = 0; h < Hsz; h++) acc += sp[h] * dw[t * Hsz + h];
        out[b * DOUT + t] = acc;
    }
}

// ---------------- launch ----------------
extern "C" void kernel_launch(void* const* d_in, const int* in_sizes, int n_in,
                              void* d_out, int out_size) {
    const float* x      = (const float*)d_in[0];
    const float* enc_w  = (const float*)d_in[1];
    const float* enc_b  = (const float*)d_in[2];
    const float* log_dt = (const float*)d_in[3];
    const float* Cp     = (const float*)d_in[4];
    const float* logAre = (const float*)d_in[5];
    const float* Aim    = (const float*)d_in[6];
    const float* Dp     = (const float*)d_in[7];
    const float* out_w  = (const float*)d_in[8];
    const float* out_b  = (const float*)d_in[9];
    const float* ln_g   = (const float*)d_in[10];
    const float* ln_b   = (const float*)d_in[11];
    const float* dec_w  = (const float*)d_in[12];
    const float* dec_b  = (const float*)d_in[13];
    float* out = (float*)d_out;

    prep_kernel<<<64, 256>>>(log_dt, Cp, logAre, Aim);
    enc_kernel<<<(Bsz * Hsz * (Lsz / 4) + 255) / 256, 256>>>(x, enc_w, enc_b);

    for (int layer = 0; layer < NL; layer++) {
        scan_kernel<<<Bsz * Hsz, 128>>>(layer, Dp);
        gluln_kernel<<<dim3(Lsz / 64, Bsz), 256>>>(out_w, out_b, ln_g, ln_b, layer);
    }

    pool_kernel<<<Bsz * Hsz, 128>>>();
    dec_kernel<<<Bsz, 128>>>(dec_w, dec_b, out);
}

// round 9
// speedup vs baseline: 1.3468x; 1.0381x over previous
#include <cuda_runtime.h>
#include <cuda_bf16.h>
#include <math.h>

#define Bsz 16
#define Lsz 4096
#define Hsz 128
#define N2 32
#define NL 4
#define O2 256
#define DOUT 100
#define Q 128
#define NC (Lsz / Q)   // 32

typedef unsigned long long u64;
typedef unsigned int u32;

// ---------------- f32x2 packed helpers ----------------
__device__ __forceinline__ u64 pk(float a, float b) {
    u64 r; asm("mov.b64 %0,{%1,%2};" : "=l"(r) : "f"(a), "f"(b)); return r;
}
__device__ __forceinline__ float2 upk(u64 v) {
    float2 r; asm("mov.b64 {%0,%1},%2;" : "=f"(r.x), "=f"(r.y) : "l"(v)); return r;
}
__device__ __forceinline__ u64 fma2(u64 a, u64 b, u64 c) {
    u64 r; asm("fma.rn.f32x2 %0,%1,%2,%3;" : "=l"(r) : "l"(a), "l"(b), "l"(c)); return r;
}
__device__ __forceinline__ u64 mul2(u64 a, u64 b) {
    u64 r; asm("mul.rn.f32x2 %0,%1,%2;" : "=l"(r) : "l"(a), "l"(b)); return r;
}
__device__ __forceinline__ u64 add2(u64 a, u64 b) {
    u64 r; asm("add.rn.f32x2 %0,%1,%2;" : "=l"(r) : "l"(a), "l"(b)); return r;
}
__device__ __forceinline__ u32 to_tf32(float x) {
    u32 r; asm("cvt.rna.tf32.f32 %0, %1;" : "=r"(r) : "f"(x)); return r;
}
__device__ __forceinline__ void mma_tf32(float c[4], const u32 a[4], const u32 b[2]) {
    asm volatile("mma.sync.aligned.m16n8k8.row.col.f32.tf32.tf32.f32 "
                 "{%0,%1,%2,%3}, {%4,%5,%6,%7}, {%8,%9}, {%0,%1,%2,%3};"
                 : "+f"(c[0]), "+f"(c[1]), "+f"(c[2]), "+f"(c[3])
                 : "r"(a[0]), "r"(a[1]), "r"(a[2]), "r"(a[3]), "r"(b[0]), "r"(b[1]));
}

// ---------------- scratch (device globals; no allocation) ----------------
__device__ float  d_hact[Bsz * Hsz * Lsz];   // activation, layout (B,H,L)
__device__ float  d_gbuf[Bsz * Hsz * Lsz];   // gelu output (GEMM input)
__device__ float4 d_rc[NL * Hsz * N2];       // {r.re, r.im, 2Cd.re, 2Cd.im}
__device__ float2 d_rq[NL * Hsz * N2];       // r^Q
__device__ float  d_pool[Bsz * Hsz];

// ---------------- prep: discretize SSM params ----------------
__global__ void prep_kernel(const float* __restrict__ log_dt,
                            const float* __restrict__ Cp,
                            const float* __restrict__ logAre,
                            const float* __restrict__ Aimp) {
    int idx = blockIdx.x * 256 + threadIdx.x;
    if (idx >= NL * Hsz * N2) return;
    int h = (idx >> 5) & 127;
    int layer = idx >> 12;
    float dt  = expf(log_dt[layer * Hsz + h]);
    float Are = -expf(logAre[idx]);
    float Ai  = Aimp[idx];
    float dre = Are * dt, dim = Ai * dt;
    float er  = expf(dre);
    float rre = er * cosf(dim), rim = er * sinf(dim);
    float den = Are * Are + Ai * Ai;
    float nre = rre - 1.0f, nim = rim;
    float fre = (nre * Are + nim * Ai) / den;
    float fim = (nim * Are - nre * Ai) / den;
    float Cre = Cp[idx * 2], Cim = Cp[idx * 2 + 1];
    float cdre = 2.0f * (Cre * fre - Cim * fim);
    float cdim = 2.0f * (Cre * fim + Cim * fre);
    d_rc[idx] = make_float4(rre, rim, cdre, cdim);
    float qr = rre, qi = rim;
#pragma unroll
    for (int i = 0; i < 7; i++) {
        float a = qr * qr - qi * qi;
        float b = 2.0f * qr * qi;
        qr = a; qi = b;
    }
    d_rq[idx] = make_float2(qr, qi);
}

// ---------------- encoder: (B,L,1) -> (B,H,L) ----------------
__global__ void enc_kernel(const float* __restrict__ x,
                           const float* __restrict__ ew,
                           const float* __restrict__ eb) {
    int idx = blockIdx.x * 256 + threadIdx.x;
    if (idx >= Bsz * Hsz * (Lsz / 4)) return;
    int l4 = idx & ((Lsz / 4) - 1);
    int h  = (idx >> 10) & 127;
    int b  = idx >> 17;
    float4 xv = ((const float4*)x)[b * (Lsz / 4) + l4];
    float w = ew[h], bb = eb[h];
    float4 o = make_float4(xv.x * w + bb, xv.y * w + bb, xv.z * w + bb, xv.w * w + bb);
    *(float4*)(d_hact + ((size_t)(b * Hsz + h)) * Lsz + l4 * 4) = o;
}

// ---- fused scan (c-folded state, 128 threads: 32 chunks x 4 groups) ----
// state w~ = w / c ; update w~' = r*w~ + u ; output y = sum Re(c * w~')
__global__ void __launch_bounds__(128) scan_kernel(int layer, const float* __restrict__ Dp) {
    __shared__ float2 swT[NC * N2];
    int bh = blockIdx.x;
    int tid = threadIdx.x;            // 128
    int chunk = tid >> 2, qt = tid & 3;
    int h = bh & 127;

    const float4* rcp = &d_rc[((layer << 7) + h) * N2 + (qt << 3)];  // 8 modes
    u64 rre[4], rim[4], nri[4], cre[4], nci[4];
#pragma unroll
    for (int k = 0; k < 4; k++) {
        float4 a = rcp[2 * k], c = rcp[2 * k + 1];
        rre[k] = pk(a.x, c.x);
        rim[k] = pk(a.y, c.y);
        nri[k] = pk(-a.y, -c.y);
        cre[k] = pk(a.z, c.z);
        nci[k] = pk(-a.w, -c.w);
    }
    u64 z = pk(0.0f, 0.0f);
    u64 wre[4], wim[4];
#pragma unroll
    for (int k = 0; k < 4; k++) { wre[k] = z; wim[k] = z; }

    const float4* up4 = (const float4*)(d_hact + (size_t)bh * Lsz + chunk * Q);

    // ---- phase A: chunk-local homogeneous scan (5 f32x2 per k-pair/step) ----
#pragma unroll 1
    for (int j4 = 0; j4 < Q / 4; j4++) {
        float4 uv = up4[j4];
        float us[4] = {uv.x, uv.y, uv.z, uv.w};
#pragma unroll
        for (int s = 0; s < 4; s++) {
            u64 u2 = pk(us[s], us[s]);
#pragma unroll
            for (int k = 0; k < 4; k++) {
                u64 nr = fma2(rre[k], wre[k], fma2(nri[k], wim[k], u2));
                wim[k] = fma2(rim[k], wre[k], mul2(rre[k], wim[k]));
                wre[k] = nr;
            }
        }
    }
    {
        float2* we = &swT[chunk * N2 + (qt << 3)];
#pragma unroll
        for (int k = 0; k < 4; k++) {
            float2 a = upk(wre[k]), bI = upk(wim[k]);
            we[2 * k]     = make_float2(a.x, bI.x);
            we[2 * k + 1] = make_float2(a.y, bI.y);
        }
    }
    __syncthreads();

    // ---- carry scan across chunks (warp 0, lane = mode) ----
    if (tid < 32) {
        float2 q = d_rq[((layer << 7) + h) * N2 + tid];
        float tr = 0.0f, ti = 0.0f;
#pragma unroll
        for (int c = 0; c < NC; c++) {
            float2 e = swT[c * N2 + tid];
            swT[c * N2 + tid] = make_float2(tr, ti);
            float a = tr * q.x - ti * q.y + e.x;
            ti = tr * q.y + ti * q.x + e.y;
            tr = a;
        }
    }
    __syncthreads();

    // ---- phase B: rescan with carried state, emit y + D*u, GELU ----
    {
        const float2* Tp = &swT[chunk * N2 + (qt << 3)];
#pragma unroll
        for (int k = 0; k < 4; k++) {
            float2 t0 = Tp[2 * k], t1 = Tp[2 * k + 1];
            wre[k] = pk(t0.x, t1.x);
            wim[k] = pk(t0.y, t1.y);
        }
    }
    float dh = Dp[(layer << 7) + h];
    float* gp = d_gbuf + (size_t)bh * Lsz + chunk * Q;
    int lane = tid & 31, gbase = lane & ~3;
#pragma unroll 1
    for (int j4 = 0; j4 < Q / 4; j4++) {
        float4 uv = up4[j4];
        float us[4] = {uv.x, uv.y, uv.z, uv.w};
        float ys[4];
#pragma unroll
        for (int s = 0; s < 4; s++) {
            u64 u2 = pk(us[s], us[s]);
            u64 y1 = z, y2 = z;
#pragma unroll
            for (int k = 0; k < 4; k++) {
                u64 nr = fma2(rre[k], wre[k], fma2(nri[k], wim[k], u2));
                wim[k] = fma2(rim[k], wre[k], mul2(rre[k], wim[k]));
                wre[k] = nr;
                y1 = fma2(cre[k], nr, y1);
                y2 = fma2(nci[k], wim[k], y2);
            }
            float2 yy = upk(add2(y1, y2));
            float y = yy.x + yy.y;
            y += __shfl_xor_sync(0xffffffffu, y, 1);
            y += __shfl_xor_sync(0xffffffffu, y, 2);
            ys[s] = y + dh * us[s];
        }
        // each lane erfs its quarter, reassemble by shuffle
        float a0 = ys[qt];
        float g = 0.5f * a0 * (1.0f + erff(a0 * 0.70710678118654752f));
        float o0 = __shfl_sync(0xffffffffu, g, gbase + 0);
        float o1 = __shfl_sync(0xffffffffu, g, gbase + 1);
        float o2 = __shfl_sync(0xffffffffu, g, gbase + 2);
        float o3 = __shfl_sync(0xffffffffu, g, gbase + 3);
        if (qt == 0) *(float4*)(gp + j4 * 4) = make_float4(o0, o1, o2, o3);
    }
}

// ------- GLU GEMM (tf32 mma, reg-prefetch) + bias + GLU + residual + LN ----
#define WPITCH 36
#define GPITCH 72
__global__ void __launch_bounds__(256) gluln_kernel(const float* __restrict__ Wp,
                                                    const float* __restrict__ bp,
                                                    const float* __restrict__ lgp,
                                                    const float* __restrict__ lbp,
                                                    int layer) {
    __shared__ __align__(16) char smbuf[46080];   // Ws[256][36] u32 | Gs[32][72] u32 ; reused as sout[128][72] f32
    __shared__ float smu[64], srs[64];
    __shared__ float sp1[4][64], sp2[4][64];
    u32*   Ws   = (u32*)smbuf;                    // 36864 B
    u32*   Gs   = (u32*)(smbuf + 36864);          // 9216 B
    float* sout = (float*)smbuf;

    int t = threadIdx.x;
    int w = t >> 5;
    int lane = t & 31;
    int grp = lane >> 2, t4 = lane & 3;
    int b = blockIdx.y;
    int l0 = blockIdx.x << 6;
    const float* Wl = Wp + layer * O2 * Hsz;

    float acc[2][8][4];
#pragma unroll
    for (int m = 0; m < 2; m++)
#pragma unroll
        for (int n = 0; n < 8; n++)
#pragma unroll
            for (int i = 0; i < 4; i++) acc[m][n][i] = 0.0f;

    int wo = t >> 3, wk4 = t & 7;      // W staging: o-lane, k4-lane
    int gl4 = t & 15, gk = t >> 4;     // G staging

    float4 wreg[8], greg[2];
#pragma unroll
    for (int r = 0; r < 8; r++)
        wreg[r] = *(const float4*)(Wl + (r * 32 + wo) * Hsz + wk4 * 4);
#pragma unroll
    for (int r = 0; r < 2; r++)
        greg[r] = *(const float4*)(d_gbuf + ((size_t)(b * Hsz + r * 16 + gk)) * Lsz + l0 + gl4 * 4);

#pragma unroll 1
    for (int kc = 0; kc < 4; kc++) {
#pragma unroll
        for (int r = 0; r < 8; r++) {
            u32* d = &Ws[(r * 32 + wo) * WPITCH + wk4 * 4];
            d[0] = to_tf32(wreg[r].x); d[1] = to_tf32(wreg[r].y);
            d[2] = to_tf32(wreg[r].z); d[3] = to_tf32(wreg[r].w);
        }
#pragma unroll
        for (int r = 0; r < 2; r++) {
            u32* d = &Gs[(r * 16 + gk) * GPITCH + gl4 * 4];
            d[0] = to_tf32(greg[r].x); d[1] = to_tf32(greg[r].y);
            d[2] = to_tf32(greg[r].z); d[3] = to_tf32(greg[r].w);
        }
        __syncthreads();

        if (kc < 3) {
            int kn = (kc + 1) * 32;
#pragma unroll
            for (int r = 0; r < 8; r++)
                wreg[r] = *(const float4*)(Wl + (r * 32 + wo) * Hsz + kn + wk4 * 4);
#pragma unroll
            for (int r = 0; r < 2; r++)
                greg[r] = *(const float4*)(d_gbuf + ((size_t)(b * Hsz + kn + r * 16 + gk)) * Lsz + l0 + gl4 * 4);
        }

#pragma unroll
        for (int k8 = 0; k8 < 4; k8++) {
            int kb = k8 * 8;
            u32 a[2][4];
#pragma unroll
            for (int m = 0; m < 2; m++) {
                int ob = (m << 7) + (w << 4);
                a[m][0] = Ws[(ob + grp) * WPITCH + kb + t4];
                a[m][1] = Ws[(ob + grp + 8) * WPITCH + kb + t4];
                a[m][2] = Ws[(ob + grp) * WPITCH + kb + t4 + 4];
                a[m][3] = Ws[(ob + grp + 8) * WPITCH + kb + t4 + 4];
            }
            u32 bf[8][2];
#pragma unroll
            for (int n = 0; n < 8; n++) {
                bf[n][0] = Gs[(kb + t4) * GPITCH + n * 8 + grp];
                bf[n][1] = Gs[(kb + t4 + 4) * GPITCH + n * 8 + grp];
            }
#pragma unroll
            for (int m = 0; m < 2; m++)
#pragma unroll
                for (int n = 0; n < 8; n++)
                    mma_tf32(acc[m][n], a[m], bf[n]);
        }
        __syncthreads();
    }

    // epilogue: bias + GLU + residual -> sout
    const float* bl = bp + layer * O2;
    int row0 = (w << 4) + grp;
    float ba0 = bl[row0],       ba1 = bl[row0 + 8];
    float bg0 = bl[row0 + 128], bg1 = bl[row0 + 136];
#pragma unroll
    for (int n = 0; n < 8; n++) {
        int col = n * 8 + 2 * t4;
        size_t g0 = ((size_t)(b * Hsz) + row0) * Lsz + l0 + col;
        float2 r0 = *(const float2*)(d_hact + g0);
        float2 r1 = *(const float2*)(d_hact + g0 + (size_t)8 * Lsz);
        float za0 = acc[0][n][0] + ba0, za1 = acc[0][n][1] + ba0;
        float za2 = acc[0][n][2] + ba1, za3 = acc[0][n][3] + ba1;
        float zg0 = acc[1][n][0] + bg0, zg1 = acc[1][n][1] + bg0;
        float zg2 = acc[1][n][2] + bg1, zg3 = acc[1][n][3] + bg1;
        zg0 = 1.0f / (1.0f + expf(-zg0));
        zg1 = 1.0f / (1.0f + expf(-zg1));
        zg2 = 1.0f / (1.0f + expf(-zg2));
        zg3 = 1.0f / (1.0f + expf(-zg3));
        float o0 = za0 * zg0 + r0.x, o1 = za1 * zg1 + r0.y;
        float o2 = za2 * zg2 + r1.x, o3 = za3 * zg3 + r1.y;
        *(float2*)&sout[row0 * GPITCH + col]       = make_float2(o0, o1);
        *(float2*)&sout[(row0 + 8) * GPITCH + col] = make_float2(o2, o3);
    }
    __syncthreads();

    // LayerNorm over channel dim (128) for each of the 64 l's
    {
        int lq = t & 63, qq = t >> 6;
        float sm = 0.0f, sq = 0.0f;
#pragma unroll 8
        for (int hh = qq * 32; hh < qq * 32 + 32; hh++) {
            float v = sout[hh * GPITCH + lq];
            sm += v; sq += v * v;
        }
        sp1[qq][lq] = sm; sp2[qq][lq] = sq;
    }
    __syncthreads();
    if (t < 64) {
        float s  = sp1[0][t] + sp1[1][t] + sp1[2][t] + sp1[3][t];
        float s2 = sp2[0][t] + sp2[1][t] + sp2[2][t] + sp2[3][t];
        float m = s * (1.0f / 128.0f);
        float var = s2 * (1.0f / 128.0f) - m * m;
        smu[t] = m;
        srs[t] = rsqrtf(var + 1e-5f);
    }
    __syncthreads();

    for (int i = t; i < 2048; i += 256) {
        int hh = i >> 4, jj = (i & 15) << 2;
        float g = lgp[(layer << 7) + hh], bb = lbp[(layer << 7) + hh];
        const float* sp = &sout[hh * GPITCH + jj];
        float4 o;
        o.x = (sp[0] - smu[jj])     * srs[jj]     * g + bb;
        o.y = (sp[1] - smu[jj + 1]) * srs[jj + 1] * g + bb;
        o.z = (sp[2] - smu[jj + 2]) * srs[jj + 2] * g + bb;
        o.w = (sp[3] - smu[jj + 3]) * srs[jj + 3] * g + bb;
        *(float4*)(d_hact + ((size_t)(b * Hsz + hh)) * Lsz + l0 + jj) = o;
    }
}

// ---------------- mean pool over L ----------------
__global__ void pool_kernel() {
    int bh = blockIdx.x;
    int t = threadIdx.x;
    const float4* p = (const float4*)(d_hact + (size_t)bh * Lsz);
    float sm = 0.0f;
    for (int i = t; i < Lsz / 4; i += 128) {
        float4 v = p[i];
        sm += v.x + v.y + v.z + v.w;
    }
#pragma unroll
    for (int o = 16; o; o >>= 1) sm += __shfl_xor_sync(0xffffffffu, sm, o);
    __shared__ float sh[4];
    if ((t & 31) == 0) sh[t >> 5] = sm;
    __syncthreads();
    if (t == 0) d_pool[bh] = (sh[0] + sh[1] + sh[2] + sh[3]) * (1.0f / Lsz);
}

// ---------------- decoder ----------------
__global__ void dec_kernel(const float* __restrict__ dw,
                           const float* __restrict__ db,
                           float* __restrict__ out) {
    int b = blockIdx.x;
    int t = threadIdx.x;
    __shared__ float sp[Hsz];
    sp[t] = d_pool[b * Hsz + t];
    __syncthreads();
    if (t < DOUT) {
        float acc = db[t];
#pragma unroll 8
        for (int h = 0; h < Hsz; h++) acc += sp[h] * dw[t * Hsz + h];
        out[b * DOUT + t] = acc;
    }
}

// ---------------- launch ----------------
extern "C" void kernel_launch(void* const* d_in, const int* in_sizes, int n_in,
                              void* d_out, int out_size) {
    const float* x      = (const float*)d_in[0];
    const float* enc_w  = (const float*)d_in[1];
    const float* enc_b  = (const float*)d_in[2];
    const float* log_dt = (const float*)d_in[3];
    const float* Cp     = (const float*)d_in[4];
    const float* logAre = (const float*)d_in[5];
    const float* Aim    = (const float*)d_in[6];
    const float* Dp     = (const float*)d_in[7];
    const float* out_w  = (const float*)d_in[8];
    const float* out_b  = (const float*)d_in[9];
    const float* ln_g   = (const float*)d_in[10];
    const float* ln_b   = (const float*)d_in[11];
    const float* dec_w  = (const float*)d_in[12];
    const float* dec_b  = (const float*)d_in[13];
    float* out = (float*)d_out;

    prep_kernel<<<64, 256>>>(log_dt, Cp, logAre, Aim);
    enc_kernel<<<(Bsz * Hsz * (Lsz / 4) + 255) / 256, 256>>>(x, enc_w, enc_b);

    for (int layer = 0; layer < NL; layer++) {
        scan_kernel<<<Bsz * Hsz, 128>>>(layer, Dp);
        gluln_kernel<<<dim3(Lsz / 64, Bsz), 256>>>(out_w, out_b, ln_g, ln_b, layer);
    }

    pool_kernel<<<Bsz * Hsz, 128>>>();
    dec_kernel<<<Bsz, 128>>>(dec_w, dec_b, out);
}